// round 12
// baseline (speedup 1.0000x reference)
#include <cuda_runtime.h>
#include <cstdint>

#define U_CNT 100000
#define I_CNT 50000
#define DIM   64
#define N_CNT 150000
#define NNZ_E 1000000
#define NNZ_T (2 * NNZ_E)                 // combined edge count
#define NDTH  (N_CNT * 16)                // output-copy threads (N * D/4)

#define SCAN_B 1024
#define NBLK   ((N_CNT + SCAN_B - 1) / SCAN_B)   // 147

// ---- static device scratch (no runtime allocation; zero-init at load) ----
__device__ int  g_cnt_a[N_CNT];           // per-row counts; scan resets to 0 each replay
__device__ int  g_cnt_r[N_CNT];
__device__ int  g_rowptr[N_CNT + 1];      // combined exclusive prefix (A+R per row)
__device__ int  g_mid[N_CNT];             // rowptr[n] + degA[n]  (A|R boundary)
__device__ int  g_rank_a[NNZ_E];          // edge rank within its row (from hist)
__device__ int  g_rank_r[NNZ_E];
__device__ unsigned int g_tile[NBLK];     // decoupled-lookback: (value<<2)|status
__device__ int2 g_sorted[NNZ_T];          // (col, val bits); per row: A edges then R edges

static __device__ __forceinline__ const float4* ego_row(
    const float* __restrict__ ue, const float* __restrict__ ie, int n) {
    return (n < U_CNT)
        ? reinterpret_cast<const float4*>(ue + (size_t)n * DIM)
        : reinterpret_cast<const float4*>(ie + (size_t)(n - U_CNT) * DIM);
}

static __device__ __forceinline__ void fma4(float4& acc, float v, const float4& x) {
    acc.x = fmaf(v, x.x, acc.x);
    acc.y = fmaf(v, x.y, acc.y);
    acc.z = fmaf(v, x.z, acc.z);
    acc.w = fmaf(v, x.w, acc.w);
}

// K1: row histogram (rank = atomic return) + stacked slot-0 copy (independent
// streaming work to use idle DRAM under the atomic latency). grid covers NDTH.
__global__ void lgcn_hist(const int* __restrict__ a_rows,
                          const int* __restrict__ r_rows,
                          const float* __restrict__ ue,
                          const float* __restrict__ ie,
                          float* __restrict__ out) {
    int i = blockIdx.x * blockDim.x + threadIdx.x;
    if (i < NBLK) g_tile[i] = 0u;
    if (i < NNZ_E) {
        g_rank_a[i] = atomicAdd(&g_cnt_a[__ldg(&a_rows[i])], 1);
        g_rank_r[i] = atomicAdd(&g_cnt_r[__ldg(&r_rows[i])], 1);
    }
    if (i < NDTH) {
        int n = i >> 4, q = i & 15;
        float4 e = __ldg(&ego_row(ue, ie, n)[q]);
        size_t sbase = (size_t)N_CNT * DIM + (size_t)n * 4 * DIM;
        __stcs(&reinterpret_cast<float4*>(out + sbase)[q], e);   // stacked slot 0
    }
}

// K2: single-pass exclusive scan over combined degrees (decoupled lookback).
// Reads both counts, RESETS them, writes combined rowptr and the A|R midpoint.
__global__ void lgcn_scan() {
    int b = blockIdx.x;
    int t = threadIdx.x;

    __shared__ int s[SCAN_B];
    __shared__ int ex_prefix;

    int i = b * SCAN_B + t;
    int cA = 0, cR = 0;
    if (i < N_CNT) {
        cA = g_cnt_a[i];
        cR = g_cnt_r[i];
        g_cnt_a[i] = 0;                    // self-reset for next replay
        g_cnt_r[i] = 0;
    }
    int v = cA + cR;
    s[t] = v;
    __syncthreads();
    #pragma unroll
    for (int off = 1; off < SCAN_B; off <<= 1) {
        int u = (t >= off) ? s[t - off] : 0;
        __syncthreads();
        s[t] += u;
        __syncthreads();
    }
    int incl  = s[t];
    int total = s[SCAN_B - 1];

    if (t == 0) {
        if (b == 0) {
            ex_prefix = 0;
            atomicExch(&g_tile[0], ((unsigned int)total << 2) | 2u);
        } else {
            atomicExch(&g_tile[b], ((unsigned int)total << 2) | 1u);
            int run = 0;
            for (int j = b - 1; j >= 0; j--) {
                unsigned int x;
                do { x = atomicAdd(&g_tile[j], 0u); } while ((x & 3u) == 0u);
                run += (int)(x >> 2);
                if ((x & 3u) == 2u) break;
            }
            ex_prefix = run;
            atomicExch(&g_tile[b], ((unsigned int)(run + total) << 2) | 2u);
        }
    }
    __syncthreads();

    if (i < N_CNT) {
        int pref = ex_prefix + incl - v;   // combined exclusive prefix
        g_rowptr[i] = pref;
        g_mid[i]    = pref + cA;
    }
    if (b == NBLK - 1 && t == SCAN_B - 1) g_rowptr[N_CNT] = NNZ_T;
}

// K3: atomic-free scatter into combined layout + path slot-0 copy.
__global__ void lgcn_scatter(const int*  __restrict__ a_rows,
                             const int*  __restrict__ a_cols,
                             const float* __restrict__ a_vals,
                             const int*  __restrict__ r_rows,
                             const int*  __restrict__ r_cols,
                             const float* __restrict__ r_vals,
                             const float* __restrict__ ue,
                             const float* __restrict__ ie,
                             float* __restrict__ out) {
    int i = blockIdx.x * blockDim.x + threadIdx.x;
    if (i < NNZ_E) {
        {
            int row = __ldg(&a_rows[i]);
            int pos = __ldg(&g_rowptr[row]) + g_rank_a[i];
            g_sorted[pos] = make_int2(__ldg(&a_cols[i]),
                                      __float_as_int(__ldg(&a_vals[i])));
        }
        {
            int row = __ldg(&r_rows[i]);
            int pos = __ldg(&g_mid[row]) + g_rank_r[i];
            g_sorted[pos] = make_int2(__ldg(&r_cols[i]),
                                      __float_as_int(__ldg(&r_vals[i])));
        }
    }
    if (i < NDTH) {
        int n = i >> 4, q = i & 15;
        float4 e = __ldg(&ego_row(ue, ie, n)[q]);
        size_t pbase = (size_t)N_CNT * DIM + (size_t)N_CNT * 4 * DIM
                     + (size_t)n * 4 * DIM;
        __stcs(&reinterpret_cast<float4*>(out + pbase)[q], e);   // path slot 0
    }
}

// K4: per-row gather SpMM + remaining output emit (slots 1-3 + mean).
__global__ void __launch_bounds__(256, 8)
lgcn_gather(const float* __restrict__ ue,
            const float* __restrict__ ie,
            float* __restrict__ out) {
    int idx = blockIdx.x * blockDim.x + threadIdx.x;
    if (idx >= NDTH) return;
    int n = idx >> 4;
    int q = idx & 15;

    int s0  = __ldg(&g_rowptr[n]);
    int e0  = __ldg(&g_rowptr[n + 1]);
    int mid = __ldg(&g_mid[n]);

    // prefetch the row's edge records while the ego self-load is in flight
    asm volatile("prefetch.global.L1 [%0];" :: "l"(g_sorted + s0));
    asm volatile("prefetch.global.L1 [%0];" :: "l"(g_sorted + (e0 - 1)));

    float4 e = __ldg(&ego_row(ue, ie, n)[q]);

    float4 a = make_float4(0.f, 0.f, 0.f, 0.f);
    float4 r = make_float4(0.f, 0.f, 0.f, 0.f);

    int i = s0;
    for (; i + 4 <= e0; i += 4) {
        int2 c0 = __ldg(&g_sorted[i]);
        int2 c1 = __ldg(&g_sorted[i + 1]);
        int2 c2 = __ldg(&g_sorted[i + 2]);
        int2 c3 = __ldg(&g_sorted[i + 3]);
        float4 x0 = __ldg(&ego_row(ue, ie, c0.x)[q]);
        float4 x1 = __ldg(&ego_row(ue, ie, c1.x)[q]);
        float4 x2 = __ldg(&ego_row(ue, ie, c2.x)[q]);
        float4 x3 = __ldg(&ego_row(ue, ie, c3.x)[q]);
        if (i     < mid) fma4(a, __int_as_float(c0.y), x0); else fma4(r, __int_as_float(c0.y), x0);
        if (i + 1 < mid) fma4(a, __int_as_float(c1.y), x1); else fma4(r, __int_as_float(c1.y), x1);
        if (i + 2 < mid) fma4(a, __int_as_float(c2.y), x2); else fma4(r, __int_as_float(c2.y), x2);
        if (i + 3 < mid) fma4(a, __int_as_float(c3.y), x3); else fma4(r, __int_as_float(c3.y), x3);
    }
    if (i < e0) {
        int2 c0 = __ldg(&g_sorted[i]);
        int2 c1 = (i + 1 < e0) ? __ldg(&g_sorted[i + 1]) : make_int2(0, 0);
        int2 c2 = (i + 2 < e0) ? __ldg(&g_sorted[i + 2]) : make_int2(0, 0);
        float4 x0 = __ldg(&ego_row(ue, ie, c0.x)[q]);
        if (i < mid) fma4(a, __int_as_float(c0.y), x0); else fma4(r, __int_as_float(c0.y), x0);
        if (i + 1 < e0) {
            float4 x1 = __ldg(&ego_row(ue, ie, c1.x)[q]);
            if (i + 1 < mid) fma4(a, __int_as_float(c1.y), x1); else fma4(r, __int_as_float(c1.y), x1);
        }
        if (i + 2 < e0) {
            float4 x2 = __ldg(&ego_row(ue, ie, c2.x)[q]);
            if (i + 2 < mid) fma4(a, __int_as_float(c2.y), x2); else fma4(r, __int_as_float(c2.y), x2);
        }
    }

    size_t sbase = (size_t)N_CNT * DIM + (size_t)n * 4 * DIM;
    size_t pbase = sbase + (size_t)N_CNT * 4 * DIM;
    float4* s = reinterpret_cast<float4*>(out + sbase);
    float4* p = reinterpret_cast<float4*>(out + pbase);
    __stcs(&s[16 + q], a);    // slots 1..3 identical (reference never updates ego)
    __stcs(&s[32 + q], a);
    __stcs(&s[48 + q], a);
    __stcs(&p[16 + q], r);
    __stcs(&p[32 + q], r);
    __stcs(&p[48 + q], r);

    float4 m = make_float4((e.x + 3.f * a.x) * 0.25f,
                           (e.y + 3.f * a.y) * 0.25f,
                           (e.z + 3.f * a.z) * 0.25f,
                           (e.w + 3.f * a.w) * 0.25f);
    __stcs(&reinterpret_cast<float4*>(out)[(size_t)n * 16 + q], m);
}

extern "C" void kernel_launch(void* const* d_in, const int* in_sizes, int n_in,
                              void* d_out, int out_size) {
    const float* ue     = (const float*)d_in[0];
    const float* ie     = (const float*)d_in[1];
    const int*   a_rows = (const int*)  d_in[2];
    const int*   a_cols = (const int*)  d_in[3];
    const float* a_vals = (const float*)d_in[4];
    const int*   r_rows = (const int*)  d_in[5];
    const int*   r_cols = (const int*)  d_in[6];
    const float* r_vals = (const float*)d_in[7];
    float* out = (float*)d_out;

    const int wide = (NDTH + 255) / 256;   // 9375 blocks: covers copies too
    lgcn_hist<<<wide, 256>>>(a_rows, r_rows, ue, ie, out);
    lgcn_scan<<<NBLK, SCAN_B>>>();
    lgcn_scatter<<<wide, 256>>>(a_rows, a_cols, a_vals,
                                r_rows, r_cols, r_vals, ue, ie, out);
    lgcn_gather<<<wide, 256>>>(ue, ie, out);
}

// round 13
// speedup vs baseline: 1.0695x; 1.0695x over previous
#include <cuda_runtime.h>
#include <cstdint>

#define U_CNT 100000
#define I_CNT 50000
#define DIM   64
#define N_CNT 150000
#define NNZ_E 1000000
#define NNZ_T (2 * NNZ_E)                 // combined edge count
#define NDTH  (N_CNT * 16)                // N * D/4 output threads

#define SCAN_B 1024
#define NBLK   ((N_CNT + SCAN_B - 1) / SCAN_B)   // 147

// ---- static device scratch (no runtime allocation; zero-init at load) ----
__device__ int  g_cnt_a[N_CNT];           // per-row counts; scan resets to 0 each replay
__device__ int  g_cnt_r[N_CNT];
__device__ int  g_rowptr[N_CNT + 1];      // combined exclusive prefix (A+R per row)
__device__ int  g_mid[N_CNT];             // rowptr[n] + degA[n]  (A|R boundary)
__device__ int  g_rank_a[NNZ_E];          // edge rank within its row (from hist)
__device__ int  g_rank_r[NNZ_E];
__device__ unsigned int g_tile[NBLK];     // decoupled-lookback: (value<<2)|status
__device__ int2 g_sorted[NNZ_T];          // (col, val bits); per row: A edges then R edges

static __device__ __forceinline__ const float4* ego_row(
    const float* __restrict__ ue, const float* __restrict__ ie, int n) {
    return (n < U_CNT)
        ? reinterpret_cast<const float4*>(ue + (size_t)n * DIM)
        : reinterpret_cast<const float4*>(ie + (size_t)(n - U_CNT) * DIM);
}

static __device__ __forceinline__ void fma4(float4& acc, float v, const float4& x) {
    acc.x = fmaf(v, x.x, acc.x);
    acc.y = fmaf(v, x.y, acc.y);
    acc.z = fmaf(v, x.z, acc.z);
    acc.w = fmaf(v, x.w, acc.w);
}

// K1: row histogram; atomic return value IS the edge's rank within its row.
// Also re-zeroes the lookback status array for the scan that follows.
__global__ void lgcn_hist(const int* __restrict__ a_rows,
                          const int* __restrict__ r_rows) {
    int i = blockIdx.x * blockDim.x + threadIdx.x;
    if (i < NBLK) g_tile[i] = 0u;
    if (i < NNZ_E) {
        g_rank_a[i] = atomicAdd(&g_cnt_a[__ldg(&a_rows[i])], 1);
        g_rank_r[i] = atomicAdd(&g_cnt_r[__ldg(&r_rows[i])], 1);
    }
}

// K2: single-pass exclusive scan over combined degrees (decoupled lookback).
// Reads both counts, RESETS them, writes combined rowptr and the A|R midpoint.
__global__ void lgcn_scan() {
    int b = blockIdx.x;
    int t = threadIdx.x;

    __shared__ int s[SCAN_B];
    __shared__ int ex_prefix;

    int i = b * SCAN_B + t;
    int cA = 0, cR = 0;
    if (i < N_CNT) {
        cA = g_cnt_a[i];
        cR = g_cnt_r[i];
        g_cnt_a[i] = 0;                    // self-reset for next replay
        g_cnt_r[i] = 0;
    }
    int v = cA + cR;
    s[t] = v;
    __syncthreads();
    #pragma unroll
    for (int off = 1; off < SCAN_B; off <<= 1) {
        int u = (t >= off) ? s[t - off] : 0;
        __syncthreads();
        s[t] += u;
        __syncthreads();
    }
    int incl  = s[t];
    int total = s[SCAN_B - 1];

    if (t == 0) {
        if (b == 0) {
            ex_prefix = 0;
            atomicExch(&g_tile[0], ((unsigned int)total << 2) | 2u);
        } else {
            atomicExch(&g_tile[b], ((unsigned int)total << 2) | 1u);
            int run = 0;
            for (int j = b - 1; j >= 0; j--) {
                unsigned int x;
                do { x = atomicAdd(&g_tile[j], 0u); } while ((x & 3u) == 0u);
                run += (int)(x >> 2);
                if ((x & 3u) == 2u) break;
            }
            ex_prefix = run;
            atomicExch(&g_tile[b], ((unsigned int)(run + total) << 2) | 2u);
        }
    }
    __syncthreads();

    if (i < N_CNT) {
        int pref = ex_prefix + incl - v;   // combined exclusive prefix
        g_rowptr[i] = pref;
        g_mid[i]    = pref + cA;
    }
    if (b == NBLK - 1 && t == SCAN_B - 1) g_rowptr[N_CNT] = NNZ_T;
}

// K3: atomic-free scatter into the combined layout.
// A edge -> rowptr[row] + rank_a ; R edge -> mid[row] + rank_r.
__global__ void lgcn_scatter(const int*  __restrict__ a_rows,
                             const int*  __restrict__ a_cols,
                             const float* __restrict__ a_vals,
                             const int*  __restrict__ r_rows,
                             const int*  __restrict__ r_cols,
                             const float* __restrict__ r_vals) {
    int i = blockIdx.x * blockDim.x + threadIdx.x;
    if (i >= NNZ_E) return;
    {
        int row = __ldg(&a_rows[i]);
        int pos = __ldg(&g_rowptr[row]) + g_rank_a[i];
        g_sorted[pos] = make_int2(__ldg(&a_cols[i]),
                                  __float_as_int(__ldg(&a_vals[i])));
    }
    {
        int row = __ldg(&r_rows[i]);
        int pos = __ldg(&g_mid[row]) + g_rank_r[i];
        g_sorted[pos] = make_int2(__ldg(&r_cols[i]),
                                  __float_as_int(__ldg(&r_vals[i])));
    }
}

// K4: per-row gather SpMM + full output emit. Single combined loop with
// predicated accumulator split; all-int32 output addressing.
__global__ void __launch_bounds__(256, 8)
lgcn_gather(const float* __restrict__ ue,
            const float* __restrict__ ie,
            float* __restrict__ out) {
    int idx = blockIdx.x * blockDim.x + threadIdx.x;
    if (idx >= NDTH) return;
    int n = idx >> 4;
    int q = idx & 15;

    int s0  = __ldg(&g_rowptr[n]);
    int e0  = __ldg(&g_rowptr[n + 1]);
    int mid = __ldg(&g_mid[n]);

    // prefetch the row's first edge records while the ego self-load is in flight
    asm volatile("prefetch.global.L1 [%0];" :: "l"(g_sorted + s0));

    float4 e = __ldg(&ego_row(ue, ie, n)[q]);

    float4 a = make_float4(0.f, 0.f, 0.f, 0.f);
    float4 r = make_float4(0.f, 0.f, 0.f, 0.f);

    int i = s0;
    for (; i + 4 <= e0; i += 4) {
        int2 c0 = __ldg(&g_sorted[i]);
        int2 c1 = __ldg(&g_sorted[i + 1]);
        int2 c2 = __ldg(&g_sorted[i + 2]);
        int2 c3 = __ldg(&g_sorted[i + 3]);
        float4 x0 = __ldg(&ego_row(ue, ie, c0.x)[q]);
        float4 x1 = __ldg(&ego_row(ue, ie, c1.x)[q]);
        float4 x2 = __ldg(&ego_row(ue, ie, c2.x)[q]);
        float4 x3 = __ldg(&ego_row(ue, ie, c3.x)[q]);
        if (i     < mid) fma4(a, __int_as_float(c0.y), x0); else fma4(r, __int_as_float(c0.y), x0);
        if (i + 1 < mid) fma4(a, __int_as_float(c1.y), x1); else fma4(r, __int_as_float(c1.y), x1);
        if (i + 2 < mid) fma4(a, __int_as_float(c2.y), x2); else fma4(r, __int_as_float(c2.y), x2);
        if (i + 3 < mid) fma4(a, __int_as_float(c3.y), x3); else fma4(r, __int_as_float(c3.y), x3);
    }
    if (i < e0) {
        int2 c0 = __ldg(&g_sorted[i]);
        int2 c1 = (i + 1 < e0) ? __ldg(&g_sorted[i + 1]) : make_int2(0, 0);
        int2 c2 = (i + 2 < e0) ? __ldg(&g_sorted[i + 2]) : make_int2(0, 0);
        float4 x0 = __ldg(&ego_row(ue, ie, c0.x)[q]);
        if (i < mid) fma4(a, __int_as_float(c0.y), x0); else fma4(r, __int_as_float(c0.y), x0);
        if (i + 1 < e0) {
            float4 x1 = __ldg(&ego_row(ue, ie, c1.x)[q]);
            if (i + 1 < mid) fma4(a, __int_as_float(c1.y), x1); else fma4(r, __int_as_float(c1.y), x1);
        }
        if (i + 2 < e0) {
            float4 x2 = __ldg(&ego_row(ue, ie, c2.x)[q]);
            if (i + 2 < mid) fma4(a, __int_as_float(c2.y), x2); else fma4(r, __int_as_float(c2.y), x2);
        }
    }

    // int32 element indexing into out viewed as float4[] (21.6M entries, fits int)
    float4* o4 = reinterpret_cast<float4*>(out);
    const int MEAN4 = 0;                       // mean tensor base (float4 units)
    const int STK4  = N_CNT * 16;              // stacked base
    const int PTH4  = STK4 + N_CNT * 64;       // path base
    int srow = STK4 + n * 64;
    int prow = PTH4 + n * 64;
    __stcs(&o4[srow + q],      e);   // stacked slot 0
    __stcs(&o4[srow + 16 + q], a);   // slots 1..3 identical (ego never updated)
    __stcs(&o4[srow + 32 + q], a);
    __stcs(&o4[srow + 48 + q], a);
    __stcs(&o4[prow + q],      e);   // path slot 0
    __stcs(&o4[prow + 16 + q], r);
    __stcs(&o4[prow + 32 + q], r);
    __stcs(&o4[prow + 48 + q], r);

    float4 m = make_float4((e.x + 3.f * a.x) * 0.25f,
                           (e.y + 3.f * a.y) * 0.25f,
                           (e.z + 3.f * a.z) * 0.25f,
                           (e.w + 3.f * a.w) * 0.25f);
    __stcs(&o4[MEAN4 + n * 16 + q], m);
}

extern "C" void kernel_launch(void* const* d_in, const int* in_sizes, int n_in,
                              void* d_out, int out_size) {
    const float* ue     = (const float*)d_in[0];
    const float* ie     = (const float*)d_in[1];
    const int*   a_rows = (const int*)  d_in[2];
    const int*   a_cols = (const int*)  d_in[3];
    const float* a_vals = (const float*)d_in[4];
    const int*   r_rows = (const int*)  d_in[5];
    const int*   r_cols = (const int*)  d_in[6];
    const float* r_vals = (const float*)d_in[7];
    float* out = (float*)d_out;

    lgcn_hist<<<(NNZ_E + 255) / 256, 256>>>(a_rows, r_rows);
    lgcn_scan<<<NBLK, SCAN_B>>>();
    lgcn_scatter<<<(NNZ_E + 255) / 256, 256>>>(a_rows, a_cols, a_vals,
                                               r_rows, r_cols, r_vals);
    lgcn_gather<<<(NDTH + 255) / 256, 256>>>(ue, ie, out);
}